// round 15
// baseline (speedup 1.0000x reference)
#include <cuda_runtime.h>
#include <cuda_bf16.h>
#include <cstdint>

// ---------------------------------------------------------------------------
// FixedHiddenMLP -> scalar: scale_to_le1( sum relu( X@M + c ) )
//   M[k][m] = sum_j W[j,k]*R[j,m],  c[m] = sum_j b[j]*R[j,m] + 1
//
// Round 13: warp-decoupled pipeline (round-12 ncu: everything ~50% =>
// CTA-wide sync serialization). Each warp owns a private 96-row slice,
// private double buffer, private mbarrier pair, private TMA bulk copy.
// ZERO __syncthreads in the hot loop.
// ---------------------------------------------------------------------------

#define D      20
#define NT     128
#define NB     444               // 148 SMs * 3 resident CTAs
#define TRW    384               // rows per CTA tile
#define WSL    96                // rows per warp slice (3 per lane)
#define SLBYT  7680u             // bytes per warp slice (96*80)

// dynamic smem layout (bytes); buffers: 2 x 4 slices x 7680 = 61440
#define OFF_XS     0u
#define OFF_SM2    61440u        // 200 u64 = 1600
#define OFF_SC2    63040u        // 10 u64 = 80
#define OFF_MBAR   63120u        // 8 mbar x 8B (warp w, buf b: +w*16+b*8)
#define OFF_SRED   63184u        // 128 x 8 = 1024
#define SMEM_TOTAL 64208

typedef unsigned long long u64;

__device__ double       g_part[NB];
__device__ unsigned int g_count;

// --- f32x2 helpers ---------------------------------------------------------
__device__ __forceinline__ u64 dup2(float v) {
    u64 r; asm("mov.b64 %0, {%1, %1};" : "=l"(r) : "f"(v)); return r;
}
__device__ __forceinline__ u64 pack2(float lo, float hi) {
    u64 r; asm("mov.b64 %0, {%1, %2};" : "=l"(r) : "f"(lo), "f"(hi)); return r;
}
__device__ __forceinline__ void unpack2(u64 v, float& lo, float& hi) {
    asm("mov.b64 {%0, %1}, %2;" : "=f"(lo), "=f"(hi) : "l"(v));
}
__device__ __forceinline__ u64 fma2(u64 a, u64 b, u64 c) {
    u64 d; asm("fma.rn.f32x2 %0, %1, %2, %3;" : "=l"(d) : "l"(a), "l"(b), "l"(c));
    return d;
}
__device__ __forceinline__ u64 add2(u64 a, u64 b) {
    u64 d; asm("add.rn.f32x2 %0, %1, %2;" : "=l"(d) : "l"(a), "l"(b));
    return d;
}

// --- smem addr / TMA-bulk / mbarrier helpers -------------------------------
__device__ __forceinline__ uint32_t smem_u32(const void* p) {
    uint32_t a;
    asm("{ .reg .u64 t; cvta.to.shared.u64 t, %1; cvt.u32.u64 %0, t; }"
        : "=r"(a) : "l"(p));
    return a;
}
__device__ __forceinline__ void mbar_init(uint32_t a, uint32_t cnt) {
    asm volatile("mbarrier.init.shared.b64 [%0], %1;" :: "r"(a), "r"(cnt) : "memory");
}
__device__ __forceinline__ void mbar_expect_tx(uint32_t a, uint32_t bytes) {
    asm volatile("mbarrier.arrive.expect_tx.shared.b64 _, [%0], %1;"
                 :: "r"(a), "r"(bytes) : "memory");
}
__device__ __forceinline__ void bulk_g2s(uint32_t dst, const void* src,
                                         uint32_t bytes, uint32_t mbar) {
    asm volatile(
        "cp.async.bulk.shared::cluster.global.mbarrier::complete_tx::bytes "
        "[%0], [%1], %2, [%3];"
        :: "r"(dst), "l"(src), "r"(bytes), "r"(mbar) : "memory");
}
__device__ __forceinline__ void mbar_wait(uint32_t a, uint32_t par) {
    uint32_t done;
    asm volatile("{\n\t.reg .pred p;\n\t"
        "mbarrier.try_wait.parity.acquire.cta.shared::cta.b64 p, [%1], %2;\n\t"
        "selp.b32 %0, 1, 0, p;\n\t}" : "=r"(done) : "r"(a), "r"(par) : "memory");
    if (!done) {
        asm volatile("{\n\t.reg .pred P1;\n\tWL_%=:\n\t"
            "mbarrier.try_wait.parity.acquire.cta.shared::cta.b64 P1, [%0], %1, 0x989680;\n\t"
            "@P1 bra.uni WD_%=;\n\tbra.uni WL_%=;\n\tWD_%=:\n\t}"
            :: "r"(a), "r"(par) : "memory");
    }
}

__global__ void __launch_bounds__(NT, 3)
fused_mlp_bulk(const float* __restrict__ X,
               const float* __restrict__ W,
               const float* __restrict__ bias,
               const float* __restrict__ R,
               float* __restrict__ out,
               long long nrows)
{
    extern __shared__ __align__(1024) unsigned char smem[];
    const uint32_t sb   = smem_u32(smem);
    const int      tid  = threadIdx.x;
    const int      w    = tid >> 5;
    const int      lane = tid & 31;

    u64*    sM2u = (u64*)(smem + OFF_SM2);     // (M[k][2p], M[k][2p+1])
    u64*    sC2u = (u64*)(smem + OFF_SC2);
    float*  sMf  = (float*)sM2u;
    float*  sCf  = (float*)sC2u;
    double* sred = (double*)(smem + OFF_SRED);

    // --- init mbarriers (8: per warp x per buffer) + fold tiny matmuls -----
    if (tid < 8) mbar_init(sb + OFF_MBAR + tid * 8, 1);
    for (int idx = tid; idx < D * D; idx += NT) {
        const int k = idx / D, m = idx % D;
        float acc = 0.f;
        #pragma unroll
        for (int j = 0; j < D; ++j)
            acc += W[j * D + k] * R[j * D + m];
        sMf[k * D + m] = acc;
    }
    if (tid < D) {
        float acc = 1.f;
        #pragma unroll
        for (int j = 0; j < D; ++j)
            acc += bias[j] * R[j * D + tid];
        sCf[tid] = acc;
    }
    __syncthreads();    // fold + mbar visible to all; LAST CTA-wide sync

    const long long ntiles = (nrows + TRW - 1) / TRW;

    // warp-private slice fill: zero-pad, TMA bulk, tx on this warp's mbar
    auto fillw = [&](int b, long long t) {
        if (t >= ntiles) return;
        const long long row0 = t * TRW + (long long)w * WSL;
        long long rem = nrows - row0;
        const int nr = rem <= 0 ? 0 : (rem < WSL ? (int)rem : WSL);
        const uint32_t sladdr = sb + OFF_XS + (uint32_t)b * (4 * SLBYT)
                                           + (uint32_t)w * SLBYT;
        if (nr < WSL) {   // zero-fill fake rows (STS by 32 lanes)
            float* dst = (float*)(smem + OFF_XS + b * (4 * SLBYT) + w * SLBYT);
            for (int i = nr * D + lane; i < WSL * D; i += 32) dst[i] = 0.f;
        }
        if (lane == 0) {
            const uint32_t mb = sb + OFF_MBAR + (uint32_t)(w * 16 + b * 8);
            mbar_expect_tx(mb, (uint32_t)nr * (D * 4));   // tx=0 ok: arrives
            if (nr > 0)
                bulk_g2s(sladdr, X + row0 * D, (uint32_t)nr * (D * 4), mb);
        }
    };

    double dacc = 0.0;
    int ph0 = 0, ph1 = 0;
    const long long t0 = blockIdx.x;

    fillw(0, t0);
    fillw(1, t0 + NB);

    int buf = 0;
    for (long long t = t0; t < ntiles; t += NB) {
        mbar_wait(sb + OFF_MBAR + (uint32_t)(w * 16 + buf * 8),
                  (uint32_t)(buf ? ph1 : ph0));
        if (buf) ph1 ^= 1; else ph0 ^= 1;

        const float* bp = (const float*)(smem + OFF_XS + buf * (4 * SLBYT)
                                              + w * SLBYT);

        // init accumulators from folded bias
        u64 a0[10], a1[10], a2[10];
        #pragma unroll
        for (int p = 0; p < 10; ++p) {
            const u64 cp = sC2u[p];
            a0[p] = cp; a1[p] = cp; a2[p] = cp;
        }

        #pragma unroll
        for (int q = 0; q < 5; ++q) {
            // 3 conflict-free LDS.128 (lane stride 20 words tiles all banks)
            const float4 x0 = *(const float4*)(bp + (lane +  0) * D + q * 4);
            const float4 x1 = *(const float4*)(bp + (lane + 32) * D + q * 4);
            const float4 x2 = *(const float4*)(bp + (lane + 64) * D + q * 4);
            const float* f0 = (const float*)&x0;
            const float* f1 = (const float*)&x1;
            const float* f2 = (const float*)&x2;
            #pragma unroll
            for (int kk = 0; kk < 4; ++kk) {
                const int k = 4 * q + kk;
                const u64 d0 = dup2(f0[kk]);
                const u64 d1 = dup2(f1[kk]);
                const u64 d2 = dup2(f2[kk]);
                const ulonglong2* mp = (const ulonglong2*)(sM2u + k * 10);
                #pragma unroll
                for (int h = 0; h < 5; ++h) {
                    const ulonglong2 mv = mp[h];    // broadcast LDS.128
                    a0[2*h+0] = fma2(d0, mv.x, a0[2*h+0]);
                    a0[2*h+1] = fma2(d0, mv.y, a0[2*h+1]);
                    a1[2*h+0] = fma2(d1, mv.x, a1[2*h+0]);
                    a1[2*h+1] = fma2(d1, mv.y, a1[2*h+1]);
                    a2[2*h+0] = fma2(d2, mv.x, a2[2*h+0]);
                    a2[2*h+1] = fma2(d2, mv.y, a2[2*h+1]);
                }
            }
        }

        // epilogue: relu + pairwise sums
        u64 r0 = 0ULL, r1 = 0ULL, r2 = 0ULL;
        #pragma unroll
        for (int p = 0; p < 10; ++p) {
            float lo, hi;
            unpack2(a0[p], lo, hi);
            r0 = add2(r0, pack2(fmaxf(lo, 0.f), fmaxf(hi, 0.f)));
            unpack2(a1[p], lo, hi);
            r1 = add2(r1, pack2(fmaxf(lo, 0.f), fmaxf(hi, 0.f)));
            unpack2(a2[p], lo, hi);
            r2 = add2(r2, pack2(fmaxf(lo, 0.f), fmaxf(hi, 0.f)));
        }
        const u64 rr = add2(add2(r0, r1), r2);
        float slo, shi;
        unpack2(rr, slo, shi);
        dacc += (double)(slo + shi);

        __syncwarp();                  // all lanes done reading this slice
        fillw(buf, t + 2 * NB);        // refill (warp-private, no CTA sync)
        buf ^= 1;
    }

    // --- block reduce -------------------------------------------------------
    __syncthreads();
    sred[tid] = dacc;
    __syncthreads();
    #pragma unroll
    for (int s = NT / 2; s > 0; s >>= 1) {
        if (tid < s) sred[tid] += sred[tid + s];
        __syncthreads();
    }
    if (tid == 0) g_part[blockIdx.x] = sred[0];

    // --- last-block: global reduce, fake-row correction, halving loop ------
    __shared__ bool is_last;
    if (tid == 0) {
        __threadfence();
        is_last = (atomicAdd(&g_count, 1u) == (unsigned)(gridDim.x - 1));
    }
    __syncthreads();
    if (is_last) {
        double acc = 0.0;
        for (int i = tid; i < NB; i += NT) acc += g_part[i];
        sred[tid] = acc;
        __syncthreads();
        #pragma unroll
        for (int s = NT / 2; s > 0; s >>= 1) {
            if (tid < s) sred[tid] += sred[tid + s];
            __syncthreads();
        }
        if (tid == 0) {
            // zero-padded fake rows each contributed sum_m relu(c[m])
            const long long fake = ntiles * TRW - nrows;
            float rcs = 0.f;
            for (int m = 0; m < D; ++m) rcs += fmaxf(sCf[m], 0.f);
            double total = sred[0] - (double)fake * (double)rcs;

            float v = (float)total;
            int n = 0;
            while (v > 1.0f && n < 4096) { v *= 0.5f; ++n; }   // exact /2
            out[0] = v;
            g_count = 0;         // reset for next graph replay
        }
    }
}

extern "C" void kernel_launch(void* const* d_in, const int* in_sizes, int n_in,
                              void* d_out, int out_size)
{
    const float* X = (const float*)d_in[0];
    const float* W = (const float*)d_in[1];
    const float* b = (const float*)d_in[2];
    const float* R = (const float*)d_in[3];
    float* out = (float*)d_out;

    const long long nrows = (long long)in_sizes[0] / D;

    cudaFuncSetAttribute(fused_mlp_bulk,
                         cudaFuncAttributeMaxDynamicSharedMemorySize,
                         SMEM_TOTAL);
    fused_mlp_bulk<<<NB, NT, SMEM_TOTAL>>>(X, W, b, R, out, nrows);
}

// round 17
// speedup vs baseline: 1.2244x; 1.2244x over previous
#include <cuda_runtime.h>
#include <cuda_bf16.h>
#include <cstdint>

// ---------------------------------------------------------------------------
// FixedHiddenMLP -> scalar: scale_to_le1( sum relu( X@M + c ) )
//   M[k][m] = sum_j W[j,k]*R[j,m],  c[m] = sum_j b[j]*R[j,m] + 1
//
// Round 14 = round 12 (44.5us best) with the hot-loop __syncthreads replaced
// by a producer/consumer EMPTY mbarrier:
//   - full[b]: count 1, completed by TMA tx (one 30KB bulk copy per tile,
//     single DRAM stream preserved -- round 13 showed fragmenting it is fatal)
//   - empty[b]: count 128; every thread arrives after reading (non-blocking),
//     only tid0 waits for it before refilling. Warps 1-3 run ahead.
//   - pipeline covers full tiles only; block 0 handles the (<384-row) tail
//     with direct LDG. No zero-fill, no fake-row correction.
// ---------------------------------------------------------------------------

#define D    20
#define NT   128
#define NB   444                  // 148 SMs * 3 resident CTAs
#define TRW  384                  // rows per tile = NT * 3

// dynamic smem layout (bytes); tile buffer = 384*80 = 30720
#define OFF_XS0    0u
#define OFF_XS1    30720u
#define OFF_SM2    61440u         // 200 u64 = 1600
#define OFF_SC2    63040u         // 10 u64 = 80
#define OFF_MBAR   63120u         // full0,full1,empty0,empty1 (4 x 8B)
#define OFF_SRED   63184u         // 128 x 8 = 1024
#define SMEM_TOTAL 64208

typedef unsigned long long u64;

__device__ double       g_part[NB];
__device__ unsigned int g_count;

// --- f32x2 helpers ---------------------------------------------------------
__device__ __forceinline__ u64 dup2(float v) {
    u64 r; asm("mov.b64 %0, {%1, %1};" : "=l"(r) : "f"(v)); return r;
}
__device__ __forceinline__ u64 pack2(float lo, float hi) {
    u64 r; asm("mov.b64 %0, {%1, %2};" : "=l"(r) : "f"(lo), "f"(hi)); return r;
}
__device__ __forceinline__ void unpack2(u64 v, float& lo, float& hi) {
    asm("mov.b64 {%0, %1}, %2;" : "=f"(lo), "=f"(hi) : "l"(v));
}
__device__ __forceinline__ u64 fma2(u64 a, u64 b, u64 c) {
    u64 d; asm("fma.rn.f32x2 %0, %1, %2, %3;" : "=l"(d) : "l"(a), "l"(b), "l"(c));
    return d;
}
__device__ __forceinline__ u64 add2(u64 a, u64 b) {
    u64 d; asm("add.rn.f32x2 %0, %1, %2;" : "=l"(d) : "l"(a), "l"(b));
    return d;
}

// --- smem addr / TMA-bulk / mbarrier helpers -------------------------------
__device__ __forceinline__ uint32_t smem_u32(const void* p) {
    uint32_t a;
    asm("{ .reg .u64 t; cvta.to.shared.u64 t, %1; cvt.u32.u64 %0, t; }"
        : "=r"(a) : "l"(p));
    return a;
}
__device__ __forceinline__ void mbar_init(uint32_t a, uint32_t cnt) {
    asm volatile("mbarrier.init.shared.b64 [%0], %1;" :: "r"(a), "r"(cnt) : "memory");
}
__device__ __forceinline__ void mbar_expect_tx(uint32_t a, uint32_t bytes) {
    asm volatile("mbarrier.arrive.expect_tx.shared.b64 _, [%0], %1;"
                 :: "r"(a), "r"(bytes) : "memory");
}
__device__ __forceinline__ void mbar_arrive(uint32_t a) {
    asm volatile("mbarrier.arrive.release.cta.shared.b64 _, [%0];"
                 :: "r"(a) : "memory");
}
__device__ __forceinline__ void bulk_g2s(uint32_t dst, const void* src,
                                         uint32_t bytes, uint32_t mbar) {
    asm volatile(
        "cp.async.bulk.shared::cluster.global.mbarrier::complete_tx::bytes "
        "[%0], [%1], %2, [%3];"
        :: "r"(dst), "l"(src), "r"(bytes), "r"(mbar) : "memory");
}
__device__ __forceinline__ void mbar_wait(uint32_t a, uint32_t par) {
    uint32_t done;
    asm volatile("{\n\t.reg .pred p;\n\t"
        "mbarrier.try_wait.parity.acquire.cta.shared::cta.b64 p, [%1], %2;\n\t"
        "selp.b32 %0, 1, 0, p;\n\t}" : "=r"(done) : "r"(a), "r"(par) : "memory");
    if (!done) {
        asm volatile("{\n\t.reg .pred P1;\n\tWL_%=:\n\t"
            "mbarrier.try_wait.parity.acquire.cta.shared::cta.b64 P1, [%0], %1, 0x989680;\n\t"
            "@P1 bra.uni WD_%=;\n\tbra.uni WL_%=;\n\tWD_%=:\n\t}"
            :: "r"(a), "r"(par) : "memory");
    }
}

__global__ void __launch_bounds__(NT, 3)
fused_mlp_bulk(const float* __restrict__ X,
               const float* __restrict__ W,
               const float* __restrict__ bias,
               const float* __restrict__ R,
               float* __restrict__ out,
               long long nrows)
{
    extern __shared__ __align__(1024) unsigned char smem[];
    const uint32_t sb  = smem_u32(smem);
    const int      tid = threadIdx.x;

    u64*    sM2u = (u64*)(smem + OFF_SM2);     // (M[k][2p], M[k][2p+1])
    u64*    sC2u = (u64*)(smem + OFF_SC2);
    float*  sMf  = (float*)sM2u;
    float*  sCf  = (float*)sC2u;
    double* sred = (double*)(smem + OFF_SRED);

    // --- init barriers + fold the tiny matmuls -----------------------------
    if (tid == 0) {
        mbar_init(sb + OFF_MBAR,      1);     // full0
        mbar_init(sb + OFF_MBAR + 8,  1);     // full1
        mbar_init(sb + OFF_MBAR + 16, NT);    // empty0
        mbar_init(sb + OFF_MBAR + 24, NT);    // empty1
    }
    for (int idx = tid; idx < D * D; idx += NT) {
        const int k = idx / D, m = idx % D;
        float acc = 0.f;
        #pragma unroll
        for (int j = 0; j < D; ++j)
            acc += W[j * D + k] * R[j * D + m];
        sMf[k * D + m] = acc;
    }
    if (tid < D) {
        float acc = 1.f;
        #pragma unroll
        for (int j = 0; j < D; ++j)
            acc += bias[j] * R[j * D + tid];
        sCf[tid] = acc;
    }
    __syncthreads();      // fold + barriers visible; last CTA-wide sync

    const long long ntiles_full = nrows / TRW;         // pipeline: full tiles
    const long long tail0 = ntiles_full * TRW;

    // filler (tid0 only): one 30KB bulk copy, tx on this buffer's full mbar
    auto fill0 = [&](int b, long long t) {             // call from tid==0 only
        const uint32_t mb = sb + OFF_MBAR + (b ? 8u : 0u);
        mbar_expect_tx(mb, TRW * D * 4);
        bulk_g2s(sb + (b ? OFF_XS1 : OFF_XS0), X + t * TRW * D,
                 TRW * D * 4, mb);
    };

    double dacc = 0.0;
    int phf0 = 0, phf1 = 0, phe0 = 0, phe1 = 0;
    const long long t0 = blockIdx.x;

    if (tid == 0) {
        if (t0      < ntiles_full) fill0(0, t0);
        if (t0 + NB < ntiles_full) fill0(1, t0 + NB);
    }

    int buf = 0;
    for (long long t = t0; t < ntiles_full; t += NB) {
        // consumer: wait for this buffer's data
        mbar_wait(sb + OFF_MBAR + (buf ? 8u : 0u), (uint32_t)(buf ? phf1 : phf0));
        if (buf) phf1 ^= 1; else phf0 ^= 1;

        const float* bp = (const float*)(smem + (buf ? OFF_XS1 : OFF_XS0));

        // init accumulators from folded bias
        u64 a0[10], a1[10], a2[10];
        #pragma unroll
        for (int p = 0; p < 10; ++p) {
            const u64 cp = sC2u[p];
            a0[p] = cp; a1[p] = cp; a2[p] = cp;
        }

        #pragma unroll
        for (int q = 0; q < 5; ++q) {
            // 3 conflict-free LDS.128 (lane stride 20 words tiles all banks)
            const float4 x0 = *(const float4*)(bp + (tid +   0) * D + q * 4);
            const float4 x1 = *(const float4*)(bp + (tid + 128) * D + q * 4);
            const float4 x2 = *(const float4*)(bp + (tid + 256) * D + q * 4);
            const float* f0 = (const float*)&x0;
            const float* f1 = (const float*)&x1;
            const float* f2 = (const float*)&x2;
            #pragma unroll
            for (int kk = 0; kk < 4; ++kk) {
                const int k = 4 * q + kk;
                const u64 d0 = dup2(f0[kk]);
                const u64 d1 = dup2(f1[kk]);
                const u64 d2 = dup2(f2[kk]);
                const ulonglong2* mp = (const ulonglong2*)(sM2u + k * 10);
                #pragma unroll
                for (int h = 0; h < 5; ++h) {
                    const ulonglong2 mv = mp[h];    // broadcast LDS.128
                    a0[2*h+0] = fma2(d0, mv.x, a0[2*h+0]);
                    a0[2*h+1] = fma2(d0, mv.y, a0[2*h+1]);
                    a1[2*h+0] = fma2(d1, mv.x, a1[2*h+0]);
                    a1[2*h+1] = fma2(d1, mv.y, a1[2*h+1]);
                    a2[2*h+0] = fma2(d2, mv.x, a2[2*h+0]);
                    a2[2*h+1] = fma2(d2, mv.y, a2[2*h+1]);
                }
            }
        }

        // epilogue: relu + pairwise sums
        u64 r0 = 0ULL, r1 = 0ULL, r2 = 0ULL;
        #pragma unroll
        for (int p = 0; p < 10; ++p) {
            float lo, hi;
            unpack2(a0[p], lo, hi);
            r0 = add2(r0, pack2(fmaxf(lo, 0.f), fmaxf(hi, 0.f)));
            unpack2(a1[p], lo, hi);
            r1 = add2(r1, pack2(fmaxf(lo, 0.f), fmaxf(hi, 0.f)));
            unpack2(a2[p], lo, hi);
            r2 = add2(r2, pack2(fmaxf(lo, 0.f), fmaxf(hi, 0.f)));
        }
        const u64 rr = add2(add2(r0, r1), r2);
        float slo, shi;
        unpack2(rr, slo, shi);
        dacc += (double)(slo + shi);

        // consumer -> producer handoff: non-blocking arrive; only tid0 waits
        mbar_arrive(sb + OFF_MBAR + (buf ? 24u : 16u));
        if (tid == 0 && t + 2 * NB < ntiles_full) {
            mbar_wait(sb + OFF_MBAR + (buf ? 24u : 16u),
                      (uint32_t)(buf ? phe1 : phe0));
            fill0(buf, t + 2 * NB);
        }
        if (buf) phe1 ^= 1; else phe0 ^= 1;
        buf ^= 1;
    }

    // --- tail rows (< TRW), block 0, direct LDG ----------------------------
    if (blockIdx.x == 0) {
        for (long long r = tail0 + tid; r < nrows; r += NT) {
            const float* xr = X + r * D;
            float x[D];
            #pragma unroll
            for (int k = 0; k < D; ++k) x[k] = xr[k];
            float rs = 0.f;
            #pragma unroll
            for (int m = 0; m < D; ++m) {
                float acc = sCf[m];
                #pragma unroll
                for (int k = 0; k < D; ++k) acc = fmaf(x[k], sMf[k * D + m], acc);
                rs += fmaxf(acc, 0.f);
            }
            dacc += (double)rs;
        }
    }

    // --- block reduce -------------------------------------------------------
    __syncthreads();
    sred[tid] = dacc;
    __syncthreads();
    #pragma unroll
    for (int s = NT / 2; s > 0; s >>= 1) {
        if (tid < s) sred[tid] += sred[tid + s];
        __syncthreads();
    }
    if (tid == 0) g_part[blockIdx.x] = sred[0];

    // --- last-block: global reduce + halving loop --------------------------
    __shared__ bool is_last;
    if (tid == 0) {
        __threadfence();
        is_last = (atomicAdd(&g_count, 1u) == (unsigned)(gridDim.x - 1));
    }
    __syncthreads();
    if (is_last) {
        double acc = 0.0;
        for (int i = tid; i < NB; i += NT) acc += g_part[i];
        sred[tid] = acc;
        __syncthreads();
        #pragma unroll
        for (int s = NT / 2; s > 0; s >>= 1) {
            if (tid < s) sred[tid] += sred[tid + s];
            __syncthreads();
        }
        if (tid == 0) {
            float v = (float)sred[0];
            int n = 0;
            while (v > 1.0f && n < 4096) { v *= 0.5f; ++n; }   // exact /2
            out[0] = v;
            g_count = 0;         // reset for next graph replay
        }
    }
}

extern "C" void kernel_launch(void* const* d_in, const int* in_sizes, int n_in,
                              void* d_out, int out_size)
{
    const float* X = (const float*)d_in[0];
    const float* W = (const float*)d_in[1];
    const float* b = (const float*)d_in[2];
    const float* R = (const float*)d_in[3];
    float* out = (float*)d_out;

    const long long nrows = (long long)in_sizes[0] / D;

    cudaFuncSetAttribute(fused_mlp_bulk,
                         cudaFuncAttributeMaxDynamicSharedMemorySize,
                         SMEM_TOTAL);
    fused_mlp_bulk<<<NB, NT, SMEM_TOTAL>>>(X, W, b, R, out, nrows);
}